// round 5
// baseline (speedup 1.0000x reference)
#include <cuda_runtime.h>

// Top-8 of 128 experts per token + softmax over selected logits.
// d_out: [0, T*8) = weights f32; [T*8, 2*T*8) = indices as f32.
//
// One warp processes TWO tokens (A, B) for ILP. Per token: lane owns 4
// contiguous experts (float4). In-lane sort runs in FLOAT domain (FSETP/FMNMX
// on the fma pipe) tracking slots; sorted values are then mapped once to
// order-preserving uint keys. Expert indices ride as packed bytes (head in
// MSB). Per round: REDUX.UMAX over heads; REDUX.UMIN over (head==max ? pack
// : ~0) resolves exact min-index tie-break AND the winner's index via the MSB
// (heads across lanes always have distinct indices). Winner shifts its list
// (sentinel 0 in the tail). Epilogue: rank r value/index picked via a 3-level
// select tree (REDUX results are warp-uniform); lanes 0-7 emit token A,
// lanes 8-15 emit token B; softmax via octet-closed xor-shuffle sum.

#define NUM_EXPERTS 128
#define TOPK 8
#define WARPS_PER_BLOCK 8

static __device__ __forceinline__ unsigned ford(float f) {
    int s = __float_as_int(f);
    return (unsigned)(s ^ ((s >> 31) | 0x80000000));   // SHF + LOP3
}
static __device__ __forceinline__ float iford(unsigned u) {
    int t = (int)u;
    return __int_as_float(t ^ ((~(t >> 31)) | 0x80000000));
}

// Full selection pipeline for one token; fills m[8], c[8] (warp-uniform).
static __device__ __forceinline__ void topk_rounds(float4 v4, unsigned lane,
                                                   unsigned* m, unsigned* c) {
    float f0 = v4.x, f1 = v4.y, f2 = v4.z, f3 = v4.w;
    unsigned s0, s1, s2, s3;
    {   // CAS(0,1): slots 0,1 -> strict < tie-correct
        bool p = f0 < f1;
        float hi = fmaxf(f0, f1), lo = fminf(f0, f1);
        f0 = hi; f1 = lo; s0 = p ? 1u : 0u; s1 = p ? 0u : 1u;
    }
    {   // CAS(2,3)
        bool p = f2 < f3;
        float hi = fmaxf(f2, f3), lo = fminf(f2, f3);
        f2 = hi; f3 = lo; s2 = p ? 3u : 2u; s3 = p ? 2u : 3u;
    }
    {   // CAS(0,2): pos0 slot in {0,1} < pos2 slot in {2,3} -> ties keep pos0
        bool p = f0 < f2;
        float hi = fmaxf(f0, f2), lo = fminf(f0, f2);
        f0 = hi; f2 = lo;
        unsigned a = p ? s2 : s0, b = p ? s0 : s2; s0 = a; s2 = b;
    }
    {   // CAS(1,3)
        bool p = f1 < f3;
        float hi = fmaxf(f1, f3), lo = fminf(f1, f3);
        f1 = hi; f3 = lo;
        unsigned a = p ? s3 : s1, b = p ? s1 : s3; s1 = a; s3 = b;
    }
    {   // CAS(1,2): only place a lower slot can meet an equal value from the
        // other side -> composite (value desc, slot asc) predicate.
        bool p = (f1 < f2) || (f1 == f2 && s1 > s2);
        float hi = fmaxf(f1, f2), lo = fminf(f1, f2);
        f1 = hi; f2 = lo;
        unsigned a = p ? s2 : s1, b = p ? s1 : s2; s1 = a; s2 = b;
    }

    unsigned k0 = ford(f0), k1 = ford(f1), k2 = ford(f2), k3 = ford(f3);

    unsigned pack = (((((s0 << 8) | s1) << 8) | s2) << 8) | s3;
    pack += lane * 0x04040404u;        // expert base 4*lane into every byte

#pragma unroll
    for (int r = 0; r < TOPK; ++r) {
        unsigned mr = __reduce_max_sync(0xffffffffu, k0);
        unsigned cand = (k0 == mr) ? pack : 0xffffffffu;
        unsigned cr = __reduce_min_sync(0xffffffffu, cand);
        m[r] = mr; c[r] = cr;
        if (r < TOPK - 1) {
            bool win = (cand == cr);
            k0 = win ? k1 : k0;
            k1 = win ? k2 : k1;
            k2 = win ? k3 : k2;
            k3 = win ? 0u : k3;          // exhausted lane can never re-win
            pack = win ? (pack << 8) : pack;
        }
    }
}

static __device__ __forceinline__ unsigned sel8(const unsigned* a,
                                                bool b0, bool b1, bool b2) {
    unsigned x0 = b0 ? a[1] : a[0];
    unsigned x1 = b0 ? a[3] : a[2];
    unsigned x2 = b0 ? a[5] : a[4];
    unsigned x3 = b0 ? a[7] : a[6];
    unsigned y0 = b1 ? x1 : x0;
    unsigned y1 = b1 ? x3 : x2;
    return b2 ? y1 : y0;
}

__global__ __launch_bounds__(WARPS_PER_BLOCK * 32, 4)
void topk_softmax_kernel(const float* __restrict__ gate,
                         float* __restrict__ out_w,
                         float* __restrict__ out_i,
                         int tokens) {
    const unsigned lane = threadIdx.x & 31;
    const int halfc = (tokens + 1) >> 1;
    const int tA = blockIdx.x * WARPS_PER_BLOCK + (threadIdx.x >> 5);
    if (tA >= halfc) return;
    const int tB = tA + halfc;
    const bool validB = (tB < tokens);

    const float4* g4 = reinterpret_cast<const float4*>(gate);
    const float4 vA = g4[(size_t)tA * (NUM_EXPERTS / 4) + lane];
    float4 vB = make_float4(0.f, 0.f, 0.f, 0.f);
    if (validB) vB = g4[(size_t)tB * (NUM_EXPERTS / 4) + lane];

    unsigned mA[TOPK], cA[TOPK], mB[TOPK], cB[TOPK];
    topk_rounds(vA, lane, mA, cA);
    topk_rounds(vB, lane, mB, cB);

    // rank = lane & 7; octet 0-7 -> token A, octet 8-15 -> token B
    const bool b0 = (lane & 1) != 0;
    const bool b1 = (lane & 2) != 0;
    const bool b2 = (lane & 4) != 0;

    const unsigned mvA = sel8(mA, b0, b1, b2);
    const unsigned cvA = sel8(cA, b0, b1, b2);
    const unsigned mvB = sel8(mB, b0, b1, b2);
    const unsigned cvB = sel8(cB, b0, b1, b2);

    float eA = __expf(iford(mvA) - iford(mA[0]));
    float eB = __expf(iford(mvB) - iford(mB[0]));
    float sA = eA, sB = eB;
    sA += __shfl_xor_sync(0xffffffffu, sA, 1);
    sA += __shfl_xor_sync(0xffffffffu, sA, 2);
    sA += __shfl_xor_sync(0xffffffffu, sA, 4);   // octet-closed
    sB += __shfl_xor_sync(0xffffffffu, sB, 1);
    sB += __shfl_xor_sync(0xffffffffu, sB, 2);
    sB += __shfl_xor_sync(0xffffffffu, sB, 4);
    const float wA = __fdividef(eA, sA);
    const float wB = __fdividef(eB, sB);

    if (lane < TOPK) {
        const size_t o = (size_t)tA * TOPK + lane;
        out_w[o] = wA;
        out_i[o] = (float)(cvA >> 24);
    } else if (lane < 2 * TOPK && validB) {
        const size_t o = (size_t)tB * TOPK + (lane - TOPK);
        out_w[o] = wB;
        out_i[o] = (float)(cvB >> 24);
    }
}

extern "C" void kernel_launch(void* const* d_in, const int* in_sizes, int n_in,
                              void* d_out, int out_size) {
    (void)n_in; (void)out_size;
    const float* gate = (const float*)d_in[0];
    const int tokens = in_sizes[0] / NUM_EXPERTS;

    float* out_w = (float*)d_out;
    float* out_i = out_w + (size_t)tokens * TOPK;

    const int halfc = (tokens + 1) >> 1;
    const int blocks = (halfc + WARPS_PER_BLOCK - 1) / WARPS_PER_BLOCK;
    topk_softmax_kernel<<<blocks, WARPS_PER_BLOCK * 32>>>(gate, out_w, out_i, tokens);
}